// round 7
// baseline (speedup 1.0000x reference)
#include <cuda_runtime.h>
#include <cstdint>

// CMPModel density matrix via warp-level mma.sync tf32, sm_103.
// V=50000, D=256, S=128, B=64.
//
// R[k,d]=word_emb[q[k],d], I[k,d]=cmp_emb[q[k],d]*pos[k]
//   real[d,e] = sum_k w[k]( R[k,d]R[k,e] + I[k,d]I[k,e] )   (SYMMETRIC)
//   imag[d,e] = sum_k w[k]( I[k,d]R[k,e] - R[k,d]I[k,e] )   (ANTISYMMETRIC)
//
// 6 subtiles/batch (128d x 64e), skipping the (1,0) quarter (anti-transpose
// of (0,1), written by st 2,3 via SMEM-transpose mirror). 384 CTAs, 256 thr,
// 2 CTAs/SM.
//
// SMEM holds FRAGMENT-PACKED tiles: each thread's m16n8k8 fragment is one
// 16B granule -> 1 LDS.128 per A-frag, 1 LDS.128 per 2 B-frags (8 LDS.128
// per k-step instead of 32 LDS.32).  XOR swizzles keep all LDS.128 phases
// bank-conflict-free.

#define D_DIM 256
#define S_LEN 128
#define B_DIM 64
#define KC    32

#define A_TILE 4096               // floats: KC*128 packed
#define B_TILE 2048               // floats: KC*64 packed
#define STAGE_FLOATS (2 * A_TILE + 2 * B_TILE)   // 12288
#define SMEM_FLOATS (2 * STAGE_FLOATS)
#define SMEM_BYTES  (SMEM_FLOATS * 4)            // 98304 B
#define TPITCH 132                // mirror transpose pitch

__device__ __forceinline__ uint32_t tf32r(float f) {
    uint32_t r;
    asm("cvt.rna.tf32.f32 %0, %1;" : "=r"(r) : "f"(f));
    return r;
}

__device__ __forceinline__ void mma8(float* c, const uint32_t* a, const uint32_t* b) {
    asm("mma.sync.aligned.m16n8k8.row.col.f32.tf32.tf32.f32 "
        "{%0,%1,%2,%3}, {%4,%5,%6,%7}, {%8,%9}, {%0,%1,%2,%3};"
        : "+f"(c[0]), "+f"(c[1]), "+f"(c[2]), "+f"(c[3])
        : "r"(a[0]), "r"(a[1]), "r"(a[2]), "r"(a[3]), "r"(b[0]), "r"(b[1]));
}

__global__ void __launch_bounds__(256, 2)
cmp_mma5_kernel(const int*   __restrict__ questions,
                const float* __restrict__ qpos,
                const float* __restrict__ wemb,
                const float* __restrict__ cemb,
                const float* __restrict__ wq,
                float*       __restrict__ out)
{
    extern __shared__ float sm[];
    __shared__ int   sq[S_LEN];
    __shared__ float sp[S_LEN];
    __shared__ float sw[S_LEN];

    const int tid  = threadIdx.x;
    const int wid  = tid >> 5;
    const int lane = tid & 31;
    const int st   = blockIdx.x;           // 0..5
    const int b    = blockIdx.y;
    const int dt   = (st >= 4) ? 1 : 0;
    const int e0   = (st < 4) ? st * 64 : 128 + (st - 4) * 64;
    const bool mirror = (st == 2 || st == 3);

    if (tid < S_LEN) {
        sq[tid] = questions[b * S_LEN + tid];
        sp[tid] = qpos[b * S_LEN + tid];
        sw[tid] = wq[tid];
    }
    __syncthreads();

    const int mr = wid >> 1;       // d block (32 rows), 0..3
    const int nc = wid & 1;        // e block (32 cols), 0..1

    float accRe[2][4][4];
    float accIm[2][4][4];
#pragma unroll
    for (int i = 0; i < 2; i++)
#pragma unroll
        for (int j = 0; j < 4; j++)
#pragma unroll
            for (int q = 0; q < 4; q++) { accRe[i][j][q] = 0.f; accIm[i][j][q] = 0.f; }

    const int r = lane >> 2;       // fragment row helper 0..7
    const int c = lane & 3;        // fragment k-sub helper 0..3

    // ---- gather chunk g into fragment-packed stage buffer ----
    // A addr: value (k,m): kg=k>>3, c'=(k&7)&3, h=(k&7)>>2; r'=m&7,
    //   hi8=(m>>3)&1, mb16=m>>4; T=(kg*4+c')*8+r'; x=((r'&1)<<2)|c';
    //   fidx = (T*8 + (mb16^x))*4 + h*2 + hi8
    // B addr: value (k,n): nb8=(n>>3)&1, nb16=n>>4;
    //   fidx = (T*4 + (nb16^c'))*4 + nb8*2 + h      (T with r'=n&7)
    auto gather = [&](int g) {
        float* stage = sm + (g & 1) * STAGE_FLOATS;
        float* AR = stage;
        float* AI = stage + A_TILE;
        float* BR = stage + 2 * A_TILE;
        float* BI = stage + 2 * A_TILE + B_TILE;
#pragma unroll
        for (int i = 0; i < 6; ++i) {
            const int t = tid + i * 256;
            const bool aside = (t < 1024);
            int k, f4, fofs;
            if (aside) { k = t >> 5;  f4 = t & 31; fofs = dt * 128 + f4 * 4; }
            else { const int u = t - 1024; k = u >> 4; f4 = u & 15; fofs = e0 + f4 * 4; }

            const int   s  = g * KC + k;
            const int   q  = sq[s];
            const float pp = sp[s];
            const float4 rv = *(const float4*)(wemb + (size_t)q * D_DIM + fofs);
            const float4 cv = *(const float4*)(cemb + (size_t)q * D_DIM + fofs);

            const int kg = k >> 3, k7 = k & 7;
            const int cc = k7 & 3, hh = k7 >> 2;
            const int w0 = hh * 2;                    // word base (h*2)

            if (aside) {
                const uint32_t rr[4] = {tf32r(rv.x), tf32r(rv.y),
                                        tf32r(rv.z), tf32r(rv.w)};
                const uint32_t ii[4] = {tf32r(cv.x * pp), tf32r(cv.y * pp),
                                        tf32r(cv.z * pp), tf32r(cv.w * pp)};
#pragma unroll
                for (int s2 = 0; s2 < 4; ++s2) {
                    const int m    = f4 * 4 + s2;
                    const int rp   = m & 7;
                    const int hi8  = (m >> 3) & 1;
                    const int mb16 = m >> 4;
                    const int T    = (kg * 4 + cc) * 8 + rp;
                    const int x    = ((rp & 1) << 2) | cc;
                    const int fidx = (T * 8 + (mb16 ^ x)) * 4 + w0 + hi8;
                    AR[fidx] = __uint_as_float(rr[s2]);
                    AI[fidx] = __uint_as_float(ii[s2]);
                }
            } else {
                const float ww = sw[s];
                const float wp = ww * pp;
                const uint32_t rr[4] = {tf32r(rv.x * ww), tf32r(rv.y * ww),
                                        tf32r(rv.z * ww), tf32r(rv.w * ww)};
                const uint32_t ii[4] = {tf32r(cv.x * wp), tf32r(cv.y * wp),
                                        tf32r(cv.z * wp), tf32r(cv.w * wp)};
#pragma unroll
                for (int s2 = 0; s2 < 4; ++s2) {
                    const int n    = f4 * 4 + s2;
                    const int rp   = n & 7;
                    const int nb8  = (n >> 3) & 1;
                    const int nb16 = n >> 4;
                    const int T    = (kg * 4 + cc) * 8 + rp;
                    const int fidx = (T * 4 + (nb16 ^ cc)) * 4 + nb8 * 2 + hh;
                    BR[fidx] = __uint_as_float(rr[s2]);
                    BI[fidx] = __uint_as_float(ii[s2]);
                }
            }
        }
    };

    gather(0);
    __syncthreads();

    for (int g = 0; g < 4; ++g) {
        float* stage = sm + (g & 1) * STAGE_FLOATS;
        const uint4* AR = (const uint4*)(stage);
        const uint4* AI = (const uint4*)(stage + A_TILE);
        const uint4* BR = (const uint4*)(stage + 2 * A_TILE);
        const uint4* BI = (const uint4*)(stage + 2 * A_TILE + B_TILE);

        if (g < 3) gather(g + 1);   // fills other stage, overlaps compute

#pragma unroll
        for (int kg = 0; kg < 4; ++kg) {
            const int T  = (kg * 4 + c) * 8 + r;
            const int xA = ((r & 1) << 2) | c;

            // ---- B fragments: 4 LDS.128 ----
            uint32_t bR[4][2], bI[4][2], bN[4][2];
#pragma unroll
            for (int j = 0; j < 2; ++j) {
                const uint4 vR = BR[T * 4 + ((nc * 2 + j) ^ c)];
                const uint4 vI = BI[T * 4 + ((nc * 2 + j) ^ c)];
                bR[2*j][0] = vR.x;  bR[2*j][1] = vR.y;
                bR[2*j+1][0] = vR.z; bR[2*j+1][1] = vR.w;
                bI[2*j][0] = vI.x;  bI[2*j][1] = vI.y;
                bI[2*j+1][0] = vI.z; bI[2*j+1][1] = vI.w;
            }
#pragma unroll
            for (int nt = 0; nt < 4; ++nt) {
                bN[nt][0] = bI[nt][0] ^ 0x80000000u;
                bN[nt][1] = bI[nt][1] ^ 0x80000000u;
            }

            // ---- A fragments + MMAs (pass-major, RAW distance 4) ----
#pragma unroll
            for (int mt = 0; mt < 2; ++mt) {
                const int ga = T * 8 + ((mr * 2 + mt) ^ xA);
                const uint4 a4 = AR[ga];
                const uint4 i4 = AI[ga];
                const uint32_t aR[4] = {a4.x, a4.y, a4.z, a4.w};
                const uint32_t aI[4] = {i4.x, i4.y, i4.z, i4.w};
#pragma unroll
                for (int nt = 0; nt < 4; ++nt) mma8(accRe[mt][nt], aR, bR[nt]);
#pragma unroll
                for (int nt = 0; nt < 4; ++nt) mma8(accRe[mt][nt], aI, bI[nt]);
#pragma unroll
                for (int nt = 0; nt < 4; ++nt) mma8(accIm[mt][nt], aI, bR[nt]);
#pragma unroll
                for (int nt = 0; nt < 4; ++nt) mma8(accIm[mt][nt], aR, bN[nt]);
            }
        }
        __syncthreads();
    }

    // ---- direct epilogue ----
    float* oRe = out + (size_t)b * D_DIM * D_DIM;
    float* oIm = oRe + (size_t)B_DIM * D_DIM * D_DIM;
#pragma unroll
    for (int mt = 0; mt < 2; ++mt) {
        const int d = dt * 128 + mr * 32 + mt * 16 + r;
#pragma unroll
        for (int nt = 0; nt < 4; ++nt) {
            const int e = e0 + nc * 32 + nt * 8 + 2 * c;
            *(float2*)(oRe + (size_t)d * D_DIM + e) =
                make_float2(accRe[mt][nt][0], accRe[mt][nt][1]);
            *(float2*)(oRe + (size_t)(d + 8) * D_DIM + e) =
                make_float2(accRe[mt][nt][2], accRe[mt][nt][3]);
            *(float2*)(oIm + (size_t)d * D_DIM + e) =
                make_float2(accIm[mt][nt][0], accIm[mt][nt][1]);
            *(float2*)(oIm + (size_t)(d + 8) * D_DIM + e) =
                make_float2(accIm[mt][nt][2], accIm[mt][nt][3]);
        }
    }

    // ---- mirror epilogue (st 2,3): rows e0..e0+63, cols 0..127 ----
    if (mirror) {
        float* T = sm;   // stage 0, free after final sync of main loop
#pragma unroll
        for (int mat = 0; mat < 2; ++mat) {
            __syncthreads();
#pragma unroll
            for (int mt = 0; mt < 2; ++mt) {
                const int dl = mr * 32 + mt * 16 + r;
#pragma unroll
                for (int nt = 0; nt < 4; ++nt) {
                    const int el = nc * 32 + nt * 8 + 2 * c;
                    const float* a = mat ? accIm[mt][nt] : accRe[mt][nt];
                    T[(size_t)el * TPITCH + dl]           = a[0];
                    T[(size_t)(el + 1) * TPITCH + dl]     = a[1];
                    T[(size_t)el * TPITCH + dl + 8]       = a[2];
                    T[(size_t)(el + 1) * TPITCH + dl + 8] = a[3];
                }
            }
            __syncthreads();
            float* ob = mat ? oIm : oRe;
            const float sgn = mat ? -1.f : 1.f;
#pragma unroll
            for (int it = 0; it < 8; ++it) {
                const int el = it * 8 + wid;   // 0..63
                float4 v = *(const float4*)(T + (size_t)el * TPITCH + lane * 4);
                v.x *= sgn; v.y *= sgn; v.z *= sgn; v.w *= sgn;
                *(float4*)(ob + (size_t)(e0 + el) * D_DIM + lane * 4) = v;
            }
        }
    }
}

extern "C" void kernel_launch(void* const* d_in, const int* in_sizes, int n_in,
                              void* d_out, int out_size) {
    const int*   questions = (const int*)d_in[0];
    const float* qpos      = (const float*)d_in[1];
    const float* wemb      = (const float*)d_in[2];
    const float* cemb      = (const float*)d_in[3];
    const float* wq        = (const float*)d_in[4];
    float*       out       = (float*)d_out;

    cudaFuncSetAttribute(cmp_mma5_kernel,
                         cudaFuncAttributeMaxDynamicSharedMemorySize, SMEM_BYTES);

    dim3 grid(6 /*subtiles*/, B_DIM);
    cmp_mma5_kernel<<<grid, 256, SMEM_BYTES>>>(questions, qpos, wemb, cemb, wq, out);
}

// round 9
// speedup vs baseline: 1.4262x; 1.4262x over previous
#include <cuda_runtime.h>
#include <cuda_fp16.h>
#include <cstdint>

// CMPModel density matrix via fp16 mma.sync m16n8k16 (f32 accum), sm_103.
// V=50000, D=256, S=128, B=64.
//
// R[k,d]=word_emb[q[k],d], I[k,d]=cmp_emb[q[k],d]*pos[k]
//   real[d,e] = sum_k w[k]( R[k,d]R[k,e] + I[k,d]I[k,e] )
//   imag[d,e] = sum_k w[k]( I[k,d]R[k,e] - R[k,d]I[k,e] )
//
// CTA = (e-half, d-half, batch): 128x128 tile, BOTH real+imag. 512 thr,
// 16 warps, warp = 32(d) x 32(e).  fp16 halves MMA count (k16) and SMEM
// bytes; fragments loaded with ldmatrix.x4.trans from [k][feat] tiles
// (256B rows, chunk^(k&7) swizzle -> conflict-free ldmatrix phases).
// Imag minus sign: negate the aR fragment (XOR 0x80008000).

#define D_DIM 256
#define S_LEN 128
#define B_DIM 64
#define KC    32

#define TILE_BYTES  8192                    // 32 k x 128 feat x 2B
#define STAGE_BYTES (4 * TILE_BYTES)        // AR, AI, BR, BI = 32KB
#define SMEM_BYTES  (2 * STAGE_BYTES)       // 64KB

#define AR_OFF 0
#define AI_OFF 8192
#define BR_OFF 16384
#define BI_OFF 24576

__device__ __forceinline__ void ldmx4t(uint32_t* r, uint32_t addr) {
    asm("ldmatrix.sync.aligned.m8n8.x4.trans.shared.b16 {%0,%1,%2,%3}, [%4];"
        : "=r"(r[0]), "=r"(r[1]), "=r"(r[2]), "=r"(r[3]) : "r"(addr));
}

__device__ __forceinline__ void mma16(float* c, const uint32_t* a,
                                      const uint32_t* b) {
    asm("mma.sync.aligned.m16n8k16.row.col.f32.f16.f16.f32 "
        "{%0,%1,%2,%3}, {%4,%5,%6,%7}, {%8,%9}, {%0,%1,%2,%3};"
        : "+f"(c[0]), "+f"(c[1]), "+f"(c[2]), "+f"(c[3])
        : "r"(a[0]), "r"(a[1]), "r"(a[2]), "r"(a[3]), "r"(b[0]), "r"(b[1]));
}

__device__ __forceinline__ uint32_t h2(float x, float y) {
    __half2 h = __halves2half2(__float2half_rn(x), __float2half_rn(y));
    return *reinterpret_cast<uint32_t*>(&h);
}

__global__ void __launch_bounds__(512, 1)
cmp_fp16_kernel(const int*   __restrict__ questions,
                const float* __restrict__ qpos,
                const float* __restrict__ wemb,
                const float* __restrict__ cemb,
                const float* __restrict__ wq,
                float*       __restrict__ out)
{
    extern __shared__ char sm[];
    __shared__ int   sq[S_LEN];
    __shared__ float sp[S_LEN];
    __shared__ float sw[S_LEN];

    const int tid  = threadIdx.x;
    const int wid  = tid >> 5;
    const int lane = tid & 31;
    const int et   = blockIdx.x;
    const int dt   = blockIdx.y;
    const int b    = blockIdx.z;

    if (tid < S_LEN) {
        sq[tid] = questions[b * S_LEN + tid];
        sp[tid] = qpos[b * S_LEN + tid];
        sw[tid] = wq[tid];
    }
    __syncthreads();

    const uint32_t smem_u =
        (uint32_t)__cvta_generic_to_shared(sm);

    const int mr = wid >> 2;       // d block (32 rows), 0..3
    const int nc = wid & 3;        // e block (32 cols), 0..3

    float accRe[2][4][4];
    float accIm[2][4][4];
#pragma unroll
    for (int i = 0; i < 2; i++)
#pragma unroll
        for (int j = 0; j < 4; j++)
#pragma unroll
            for (int q = 0; q < 4; q++) { accRe[i][j][q] = 0.f; accIm[i][j][q] = 0.f; }

    // ldmatrix per-lane address components
    const int xorv  = lane & 7;
    const int krowA = (lane & 7) | ((lane & 16) >> 1);   // A tiles: m8-sel in bit3
    const int aCh   = (lane >> 3) & 1;
    const int krowB = (lane & 7) | (lane & 8);           // B tiles: n8-sel in bit4
    const int bCh   = (lane >> 4) & 1;

    // base byte offsets (within a table) for this lane
    const uint32_t aBase = (uint32_t)krowA * 256 +
        (uint32_t)(((mr * 4 + aCh) ^ xorv) * 16);        // + mt*2^xor handled below
    const uint32_t bBase = (uint32_t)krowB * 256 +
        (uint32_t)(((nc * 4 + bCh) ^ xorv) * 16);

    // ---- gather chunk g into stage buffer ----
    auto gather = [&](int g) {
        const uint32_t stg = smem_u + (uint32_t)(g & 1) * STAGE_BYTES;
#pragma unroll
        for (int i = 0; i < 4; ++i) {
            const int t    = tid + i * 512;
            const int half = t >> 10;            // 0: A (d-side), 1: B (e-side)
            const int k    = (t >> 5) & 31;
            const int f4   = t & 31;
            const int fofs = (half ? et : dt) * 128 + f4 * 4;

            const int   s  = g * KC + k;
            const int   q  = sq[s];
            const float pp = sp[s];
            const float4 rv = *(const float4*)(wemb + (size_t)q * D_DIM + fofs);
            const float4 cv = *(const float4*)(cemb + (size_t)q * D_DIM + fofs);

            const uint32_t dst = stg + (half ? BR_OFF : AR_OFF) +
                (uint32_t)k * 256 +
                (uint32_t)(((f4 >> 1) ^ (k & 7)) * 16 + (f4 & 1) * 8);

            if (half == 0) {
                uint2 vR = make_uint2(h2(rv.x, rv.y), h2(rv.z, rv.w));
                uint2 vI = make_uint2(h2(cv.x * pp, cv.y * pp),
                                      h2(cv.z * pp, cv.w * pp));
                asm volatile("st.shared.v2.b32 [%0], {%1,%2};"
                             :: "r"(dst), "r"(vR.x), "r"(vR.y));
                asm volatile("st.shared.v2.b32 [%0], {%1,%2};"
                             :: "r"(dst + (AI_OFF - AR_OFF)), "r"(vI.x), "r"(vI.y));
            } else {
                const float ww = sw[s];
                const float wp = ww * pp;
                uint2 vR = make_uint2(h2(rv.x * ww, rv.y * ww),
                                      h2(rv.z * ww, rv.w * ww));
                uint2 vI = make_uint2(h2(cv.x * wp, cv.y * wp),
                                      h2(cv.z * wp, cv.w * wp));
                asm volatile("st.shared.v2.b32 [%0], {%1,%2};"
                             :: "r"(dst), "r"(vR.x), "r"(vR.y));
                asm volatile("st.shared.v2.b32 [%0], {%1,%2};"
                             :: "r"(dst + (BI_OFF - BR_OFF)), "r"(vI.x), "r"(vI.y));
            }
        }
    };

    gather(0);
    __syncthreads();

    for (int g = 0; g < 4; ++g) {
        const uint32_t stg = smem_u + (uint32_t)(g & 1) * STAGE_BYTES;

        if (g < 3) gather(g + 1);   // other stage; overlaps compute below

#pragma unroll
        for (int kg = 0; kg < 2; ++kg) {
            const uint32_t kofs = (uint32_t)kg * 4096;   // 16 k-rows * 256B

            // ---- B fragments: 4 ldmatrix.x4 (BR, BI x 2 n16-blocks) ----
            uint32_t bR[8], bI[8];
#pragma unroll
            for (int ntp = 0; ntp < 2; ++ntp) {
                // chunk base: nc*4 + ntp*2 (+bCh) -> adjust XOR term by ntp*2
                const uint32_t badj = bBase ^ (uint32_t)(ntp * 2 * 16);
                ldmx4t(bR + 4 * ntp, stg + BR_OFF + kofs + badj);
                ldmx4t(bI + 4 * ntp, stg + BI_OFF + kofs + badj);
            }

#pragma unroll
            for (int mt = 0; mt < 2; ++mt) {
                const uint32_t aadj = aBase ^ (uint32_t)(mt * 2 * 16);
                uint32_t aR[4], aI[4], aN[4];
                ldmx4t(aR, stg + AR_OFF + kofs + aadj);
                ldmx4t(aI, stg + AI_OFF + kofs + aadj);
#pragma unroll
                for (int j = 0; j < 4; ++j) aN[j] = aR[j] ^ 0x80008000u;

                // pass-major: same-accumulator RAW distance 4
#pragma unroll
                for (int nt = 0; nt < 4; ++nt) {
                    const int bi = (nt >> 1) * 4 + (nt & 1) * 2;
                    mma16(accRe[mt][nt], aR, bR + bi);
                }
#pragma unroll
                for (int nt = 0; nt < 4; ++nt) {
                    const int bi = (nt >> 1) * 4 + (nt & 1) * 2;
                    mma16(accRe[mt][nt], aI, bI + bi);
                }
#pragma unroll
                for (int nt = 0; nt < 4; ++nt) {
                    const int bi = (nt >> 1) * 4 + (nt & 1) * 2;
                    mma16(accIm[mt][nt], aI, bR + bi);
                }
#pragma unroll
                for (int nt = 0; nt < 4; ++nt) {
                    const int bi = (nt >> 1) * 4 + (nt & 1) * 2;
                    mma16(accIm[mt][nt], aN, bI + bi);
                }
            }
        }
        __syncthreads();
    }

    // ---- epilogue ----
    const int r = lane >> 2;
    const int c = lane & 3;
    float* oRe = out + (size_t)b * D_DIM * D_DIM;
    float* oIm = oRe + (size_t)B_DIM * D_DIM * D_DIM;
#pragma unroll
    for (int mt = 0; mt < 2; ++mt) {
        const int d = dt * 128 + mr * 32 + mt * 16 + r;
#pragma unroll
        for (int nt = 0; nt < 4; ++nt) {
            const int e = et * 128 + nc * 32 + nt * 8 + 2 * c;
            *(float2*)(oRe + (size_t)d * D_DIM + e) =
                make_float2(accRe[mt][nt][0], accRe[mt][nt][1]);
            *(float2*)(oRe + (size_t)(d + 8) * D_DIM + e) =
                make_float2(accRe[mt][nt][2], accRe[mt][nt][3]);
            *(float2*)(oIm + (size_t)d * D_DIM + e) =
                make_float2(accIm[mt][nt][0], accIm[mt][nt][1]);
            *(float2*)(oIm + (size_t)(d + 8) * D_DIM + e) =
                make_float2(accIm[mt][nt][2], accIm[mt][nt][3]);
        }
    }
}

extern "C" void kernel_launch(void* const* d_in, const int* in_sizes, int n_in,
                              void* d_out, int out_size) {
    const int*   questions = (const int*)d_in[0];
    const float* qpos      = (const float*)d_in[1];
    const float* wemb      = (const float*)d_in[2];
    const float* cemb      = (const float*)d_in[3];
    const float* wq        = (const float*)d_in[4];
    float*       out       = (float*)d_out;

    cudaFuncSetAttribute(cmp_fp16_kernel,
                         cudaFuncAttributeMaxDynamicSharedMemorySize, SMEM_BYTES);

    dim3 grid(2 /*e-half*/, 2 /*d-half*/, B_DIM);
    cmp_fp16_kernel<<<grid, 512, SMEM_BYTES>>>(questions, qpos, wemb, cemb, wq, out);
}